// round 4
// baseline (speedup 1.0000x reference)
#include <cuda_runtime.h>
#include <cuda_bf16.h>
#include <cstdint>

// Problem constants (fixed by the dataset)
#define NN 100000          // nodes
#define NE 600000          // edges
#define DIM 128            // feature dim
#define FEATS (NN * DIM)   // 12,800,000 floats per activation buffer

// ---------------------------------------------------------------------------
// Scratch (device globals — no runtime allocation allowed)
// ---------------------------------------------------------------------------
__device__ __align__(16) float g_z[FEATS];     // post-aggregation z = h + sum
__device__ __align__(16) float g_hid[FEATS];   // MLP hidden
__device__ __align__(16) float g_h[FEATS];     // inter-layer activation
__device__ int g_deg[NN];
__device__ int g_cursor[NN];
__device__ int g_rowstart[NN + 1];
__device__ int g_csr_src[NE];

// ---------------------------------------------------------------------------
// CSR build: clear, histogram by dst, prefix scan, scatter-fill
// ---------------------------------------------------------------------------
__global__ void clear_counts_kernel() {
    int i = blockIdx.x * blockDim.x + threadIdx.x;
    if (i < NN) { g_deg[i] = 0; g_cursor[i] = 0; }
}

__global__ void hist_kernel(const int* __restrict__ dst) {
    int e = blockIdx.x * blockDim.x + threadIdx.x;
    if (e < NE) atomicAdd(&g_deg[dst[e]], 1);
}

// Single-block exclusive scan over NN degree counts (1024 threads, serial chunks)
#define SCHUNK 98  // 1024 * 98 = 100352 >= NN
__global__ void scan_kernel() {
    __shared__ int part[1024];
    int t = threadIdx.x;
    int start = t * SCHUNK;
    int end = min(start + SCHUNK, NN);
    int s = 0;
    for (int i = start; i < end; i++) s += g_deg[i];
    part[t] = s;
    __syncthreads();
    // Hillis–Steele inclusive scan
    for (int off = 1; off < 1024; off <<= 1) {
        int v = (t >= off) ? part[t - off] : 0;
        __syncthreads();
        part[t] += v;
        __syncthreads();
    }
    int run = (t == 0) ? 0 : part[t - 1];
    for (int i = start; i < end; i++) { g_rowstart[i] = run; run += g_deg[i]; }
    if (t == 1023) g_rowstart[NN] = part[1023];
}

__global__ void fill_kernel(const int* __restrict__ src, const int* __restrict__ dst) {
    int e = blockIdx.x * blockDim.x + threadIdx.x;
    if (e < NE) {
        int v = dst[e];
        int pos = g_rowstart[v] + atomicAdd(&g_cursor[v], 1);
        g_csr_src[pos] = src[e];
    }
}

// ---------------------------------------------------------------------------
// Gather-sum: z[v] = h[v] + sum_{u in N_in(v)} h[u].  One warp per node,
// each lane owns one float4 (32 lanes * 4 = 128 features). No atomics.
// ---------------------------------------------------------------------------
__global__ void gather_kernel(const float* __restrict__ h, float* __restrict__ z) {
    int warp = (blockIdx.x * blockDim.x + threadIdx.x) >> 5;
    int lane = threadIdx.x & 31;
    if (warp >= NN) return;
    const float4* __restrict__ h4 = (const float4*)h;
    float4 acc = h4[warp * 32 + lane];
    int beg = g_rowstart[warp];
    int end = g_rowstart[warp + 1];
    for (int j = beg; j < end; j++) {
        int s = g_csr_src[j];
        float4 v = h4[s * 32 + lane];
        acc.x += v.x; acc.y += v.y; acc.z += v.z; acc.w += v.w;
    }
    ((float4*)z)[warp * 32 + lane] = acc;
}

// ---------------------------------------------------------------------------
// Fused SGEMM + bias + optional ReLU.
// C[M,128] = act(A[M,128] @ W[128,128] + bias)
// BM=BN=128, BK=16, 256 threads, 8x8 outputs per thread.
// ---------------------------------------------------------------------------
__global__ void __launch_bounds__(256)
gemm_bias_act_kernel(const float* __restrict__ A, const float* __restrict__ W,
                     const float* __restrict__ bias, float* __restrict__ C,
                     int M, int doRelu) {
    __shared__ float As[16][132];   // transposed A tile, +4 pad
    __shared__ float Bs[16][128];

    int tid = threadIdx.x;
    int m0 = blockIdx.x * 128;
    int ty = tid >> 4;         // 0..15 -> row group
    int tx = tid & 15;         // 0..15 -> col group

    float acc[8][8];
#pragma unroll
    for (int i = 0; i < 8; i++)
#pragma unroll
        for (int j = 0; j < 8; j++) acc[i][j] = 0.0f;

    int ar = tid >> 2;          // 0..63
    int ac = (tid & 3) << 2;    // 0,4,8,12
    int br = tid >> 5;          // 0..7
    int bc = (tid & 31) << 2;   // 0..124

    for (int k0 = 0; k0 < 128; k0 += 16) {
        // load A tile (128 rows x 16 k), store transposed As[k][m]
#pragma unroll
        for (int r = 0; r < 128; r += 64) {
            int row = m0 + ar + r;
            float4 v = make_float4(0.f, 0.f, 0.f, 0.f);
            if (row < M) v = *(const float4*)&A[row * 128 + k0 + ac];
            As[ac + 0][ar + r] = v.x;
            As[ac + 1][ar + r] = v.y;
            As[ac + 2][ar + r] = v.z;
            As[ac + 3][ar + r] = v.w;
        }
        // load B tile (16 k-rows x 128 n)
#pragma unroll
        for (int r = 0; r < 16; r += 8) {
            *(float4*)&Bs[br + r][bc] = *(const float4*)&W[(k0 + br + r) * 128 + bc];
        }
        __syncthreads();

#pragma unroll
        for (int k = 0; k < 16; k++) {
            float4 a0 = *(const float4*)&As[k][ty * 8];
            float4 a1 = *(const float4*)&As[k][ty * 8 + 4];
            float4 b0 = *(const float4*)&Bs[k][tx * 8];
            float4 b1 = *(const float4*)&Bs[k][tx * 8 + 4];
            float a[8] = {a0.x, a0.y, a0.z, a0.w, a1.x, a1.y, a1.z, a1.w};
            float b[8] = {b0.x, b0.y, b0.z, b0.w, b1.x, b1.y, b1.z, b1.w};
#pragma unroll
            for (int i = 0; i < 8; i++)
#pragma unroll
                for (int j = 0; j < 8; j++) acc[i][j] = fmaf(a[i], b[j], acc[i][j]);
        }
        __syncthreads();
    }

    // epilogue: bias + optional relu
    float bb[8];
#pragma unroll
    for (int j = 0; j < 8; j++) bb[j] = bias[tx * 8 + j];

#pragma unroll
    for (int i = 0; i < 8; i++) {
        int row = m0 + ty * 8 + i;
        if (row >= M) break;
        float o[8];
#pragma unroll
        for (int j = 0; j < 8; j++) {
            float v = acc[i][j] + bb[j];
            o[j] = doRelu ? fmaxf(v, 0.0f) : v;
        }
        *(float4*)&C[row * 128 + tx * 8]     = make_float4(o[0], o[1], o[2], o[3]);
        *(float4*)&C[row * 128 + tx * 8 + 4] = make_float4(o[4], o[5], o[6], o[7]);
    }
}

// ---------------------------------------------------------------------------
// Host launcher
// ---------------------------------------------------------------------------
extern "C" void kernel_launch(void* const* d_in, const int* in_sizes, int n_in,
                              void* d_out, int out_size) {
    const float* x   = (const float*)d_in[0];
    const int*   src = (const int*)  d_in[1];
    const int*   dst = (const int*)  d_in[2];
    const float* W1  = (const float*)d_in[3];
    const float* b1  = (const float*)d_in[4];
    const float* W2  = (const float*)d_in[5];
    const float* b2  = (const float*)d_in[6];
    float* out = (float*)d_out;

    float *z, *hid, *h;
    cudaGetSymbolAddress((void**)&z,   g_z);
    cudaGetSymbolAddress((void**)&hid, g_hid);
    cudaGetSymbolAddress((void**)&h,   g_h);

    // Build CSR (by dst) once per call
    clear_counts_kernel<<<(NN + 255) / 256, 256>>>();
    hist_kernel<<<(NE + 255) / 256, 256>>>(dst);
    scan_kernel<<<1, 1024>>>();
    fill_kernel<<<(NE + 255) / 256, 256>>>(src, dst);

    const int gather_blocks = (NN * 32 + 255) / 256;  // warp per node
    const int gemm_blocks = (NN + 127) / 128;

    const float* h_in = x;
    for (int layer = 0; layer < 3; layer++) {
        gather_kernel<<<gather_blocks, 256>>>(h_in, z);
        gemm_bias_act_kernel<<<gemm_blocks, 256>>>(z, W1, b1, hid, NN, 1);
        float* h_out = (layer == 2) ? out : h;
        int relu = (layer < 2) ? 1 : 0;   // inter-layer ReLU fused into GEMM2
        gemm_bias_act_kernel<<<gemm_blocks, 256>>>(hid, W2, b2, h_out, NN, relu);
        h_in = h;
    }
}

// round 7
// speedup vs baseline: 1.4176x; 1.4176x over previous
#include <cuda_runtime.h>
#include <cuda_bf16.h>
#include <cstdint>
#include <cstddef>

// Problem constants
#define NN 100000
#define NE 600000
#define DIM 128
#define NT 782                     // ceil(NN/128)
#define PADN (NT * 128)            // 100096 padded rows
#define PFEATS (PADN * DIM)

// ---------------------------------------------------------------------------
// Device scratch (static — no runtime allocation). Zero-initialized at load;
// pad rows (>= NN) are only ever rewritten with deterministic values.
// ---------------------------------------------------------------------------
__device__ __align__(16) float g_z[PFEATS];
__device__ __align__(16) float g_hid[PFEATS];
__device__ __align__(16) float g_h[PFEATS];
__device__ __nv_bfloat16 g_w1hi[DIM * DIM];   // W^T [n][k] bf16 hi
__device__ __nv_bfloat16 g_w1lo[DIM * DIM];
__device__ __nv_bfloat16 g_w2hi[DIM * DIM];
__device__ __nv_bfloat16 g_w2lo[DIM * DIM];
__device__ int g_deg[NN];
__device__ int g_cursor[NN];
__device__ int g_rowstart[NN + 1];
__device__ int g_csr_src[NE];

// ---------------------------------------------------------------------------
// CSR build (validated in round 4)
// ---------------------------------------------------------------------------
__global__ void clear_counts_kernel() {
    int i = blockIdx.x * blockDim.x + threadIdx.x;
    if (i < NN) { g_deg[i] = 0; g_cursor[i] = 0; }
}
__global__ void hist_kernel(const int* __restrict__ dst) {
    int e = blockIdx.x * blockDim.x + threadIdx.x;
    if (e < NE) atomicAdd(&g_deg[dst[e]], 1);
}
#define SCHUNK 98
__global__ void scan_kernel() {
    __shared__ int part[1024];
    int t = threadIdx.x;
    int start = t * SCHUNK;
    int end = min(start + SCHUNK, NN);
    int s = 0;
    for (int i = start; i < end; i++) s += g_deg[i];
    part[t] = s;
    __syncthreads();
    for (int off = 1; off < 1024; off <<= 1) {
        int v = (t >= off) ? part[t - off] : 0;
        __syncthreads();
        part[t] += v;
        __syncthreads();
    }
    int run = (t == 0) ? 0 : part[t - 1];
    for (int i = start; i < end; i++) { g_rowstart[i] = run; run += g_deg[i]; }
    if (t == 1023) g_rowstart[NN] = part[1023];
}
__global__ void fill_kernel(const int* __restrict__ src, const int* __restrict__ dst) {
    int e = blockIdx.x * blockDim.x + threadIdx.x;
    if (e < NE) {
        int v = dst[e];
        int pos = g_rowstart[v] + atomicAdd(&g_cursor[v], 1);
        g_csr_src[pos] = src[e];
    }
}

// ---------------------------------------------------------------------------
// Gather-sum (warp per node), fp32 -> fp32. Validated in round 4.
// ---------------------------------------------------------------------------
__global__ void gather_kernel(const float* __restrict__ h, float* __restrict__ z) {
    int warp = (blockIdx.x * blockDim.x + threadIdx.x) >> 5;
    int lane = threadIdx.x & 31;
    if (warp >= NN) return;
    const float4* __restrict__ h4 = (const float4*)h;
    float4 acc = h4[warp * 32 + lane];
    int beg = g_rowstart[warp];
    int end = g_rowstart[warp + 1];
    for (int j = beg; j < end; j++) {
        int s = g_csr_src[j];
        float4 v = h4[s * 32 + lane];
        acc.x += v.x; acc.y += v.y; acc.z += v.z; acc.w += v.w;
    }
    ((float4*)z)[warp * 32 + lane] = acc;
}

// ---------------------------------------------------------------------------
// Weight prep: W[k][n] fp32 -> W^T[n][k] bf16 hi/lo (once per call, 16K elems)
// ---------------------------------------------------------------------------
__global__ void wprep_kernel(const float* __restrict__ W,
                             __nv_bfloat16* __restrict__ Hi,
                             __nv_bfloat16* __restrict__ Lo) {
    int idx = blockIdx.x * blockDim.x + threadIdx.x;
    if (idx >= DIM * DIM) return;
    int k = idx >> 7, n = idx & 127;
    float v = W[idx];
    __nv_bfloat16 h = __float2bfloat16(v);
    __nv_bfloat16 l = __float2bfloat16(v - __bfloat162float(h));
    Hi[n * DIM + k] = h;
    Lo[n * DIM + k] = l;
}

// ---------------------------------------------------------------------------
// Tensor-core GEMM via mma.sync (bf16 split-fp32, 3 passes, fp32 accum).
// C[128,128] = act(A @ W + bias) per CTA tile. 8 warps, warp tile 64x32.
// ---------------------------------------------------------------------------
#define PITCH 272                         // padded smem row: 136 bf16 = 272 B
#define SM_AHI 0
#define SM_ALO (128 * PITCH)              // 34816
#define SM_WHI (2 * 128 * PITCH)
#define SM_WLO (3 * 128 * PITCH)
#define SMEM_DYN (4 * 128 * PITCH)        // 139264 B

static __device__ __forceinline__ uint32_t smem_u32(const void* p) {
    uint32_t a;
    asm("{ .reg .u64 t; cvta.to.shared.u64 t, %1; cvt.u32.u64 %0, t; }" : "=r"(a) : "l"(p));
    return a;
}
static __device__ __forceinline__ void ldm_x4(uint32_t* r, uint32_t addr) {
    asm volatile("ldmatrix.sync.aligned.m8n8.x4.shared.b16 {%0,%1,%2,%3}, [%4];"
                 : "=r"(r[0]), "=r"(r[1]), "=r"(r[2]), "=r"(r[3]) : "r"(addr));
}
static __device__ __forceinline__ void ldm_x2(uint32_t* r, uint32_t addr) {
    asm volatile("ldmatrix.sync.aligned.m8n8.x2.shared.b16 {%0,%1}, [%2];"
                 : "=r"(r[0]), "=r"(r[1]) : "r"(addr));
}
static __device__ __forceinline__ void mma_bf16(float* d, const uint32_t* a, const uint32_t* b) {
    asm volatile(
        "mma.sync.aligned.m16n8k16.row.col.f32.bf16.bf16.f32 "
        "{%0,%1,%2,%3}, {%4,%5,%6,%7}, {%8,%9}, {%0,%1,%2,%3};"
        : "+f"(d[0]), "+f"(d[1]), "+f"(d[2]), "+f"(d[3])
        : "r"(a[0]), "r"(a[1]), "r"(a[2]), "r"(a[3]), "r"(b[0]), "r"(b[1]));
}
static __device__ __forceinline__ uint32_t pack_hi(float a, float b) {
    __nv_bfloat162 H; H.x = __float2bfloat16(a); H.y = __float2bfloat16(b);
    return *(uint32_t*)&H;
}

__global__ void __launch_bounds__(256)
gemm_tc_kernel(const float* __restrict__ A,
               const __nv_bfloat16* __restrict__ Wh, const __nv_bfloat16* __restrict__ Wl,
               const float* __restrict__ bias,
               float* __restrict__ C, int outRows, int doRelu) {
    extern __shared__ __align__(16) unsigned char smem[];
    uint32_t sbase = smem_u32(smem);
    int tid = threadIdx.x, wid = tid >> 5, lane = tid & 31;
    int tile = blockIdx.x;
    int rowbase = tile * 128;

    // ---- Load phase: A fp32 -> hi/lo bf16 smem; W bf16 -> smem (padded) ----
    {
        const float4* Ag = (const float4*)(A + (size_t)rowbase * DIM);
#pragma unroll
        for (int i = 0; i < 16; i++) {
            int idx = tid + i * 256;            // 4096 float4 total
            int row = idx >> 5, c4 = idx & 31;  // col = c4*4
            float4 v = Ag[idx];
            __nv_bfloat16 h0 = __float2bfloat16(v.x), h1 = __float2bfloat16(v.y);
            __nv_bfloat16 h2 = __float2bfloat16(v.z), h3 = __float2bfloat16(v.w);
            __nv_bfloat162 H01; H01.x = h0; H01.y = h1;
            __nv_bfloat162 H23; H23.x = h2; H23.y = h3;
            __nv_bfloat162 L01, L23;
            L01.x = __float2bfloat16(v.x - __bfloat162float(h0));
            L01.y = __float2bfloat16(v.y - __bfloat162float(h1));
            L23.x = __float2bfloat16(v.z - __bfloat162float(h2));
            L23.y = __float2bfloat16(v.w - __bfloat162float(h3));
            uint32_t off = row * PITCH + c4 * 8;
            *(uint32_t*)(smem + SM_AHI + off)     = *(uint32_t*)&H01;
            *(uint32_t*)(smem + SM_AHI + off + 4) = *(uint32_t*)&H23;
            *(uint32_t*)(smem + SM_ALO + off)     = *(uint32_t*)&L01;
            *(uint32_t*)(smem + SM_ALO + off + 4) = *(uint32_t*)&L23;
        }
        const uint4* wh4 = (const uint4*)Wh;
        const uint4* wl4 = (const uint4*)Wl;
#pragma unroll
        for (int i = 0; i < 8; i++) {
            int idx = tid + i * 256;            // 2048 uint4 total (128x16)
            int row = idx >> 4, c = idx & 15;   // 16B chunks
            uint32_t off = row * PITCH + c * 16;
            *(uint4*)(smem + SM_WHI + off) = wh4[idx];
            *(uint4*)(smem + SM_WLO + off) = wl4[idx];
        }
    }
    __syncthreads();

    // ---- Compute: warp tile 64(M) x 32(N), 3 split passes ----
    int warp_m = (wid >> 2) * 64;   // 0 or 64
    int warp_n = (wid & 3) * 32;    // 0,32,64,96

    float acc[4][4][4];
#pragma unroll
    for (int mi = 0; mi < 4; mi++)
#pragma unroll
        for (int nj = 0; nj < 4; nj++)
#pragma unroll
            for (int q = 0; q < 4; q++) acc[mi][nj][q] = 0.0f;

    // ldmatrix lane addressing
    int arow = ((lane >> 3) & 1) * 8 + (lane & 7);   // 0..15
    int acol = (lane >> 4) << 3;                     // 0 or 8
    int brow = lane & 7;
    int bk = ((lane >> 3) & 1) * 8;

    uint32_t a_lane = (uint32_t)((warp_m + arow) * PITCH + acol * 2);
    uint32_t b_lane = (uint32_t)((warp_n + brow) * PITCH + bk * 2);

#pragma unroll
    for (int pass = 0; pass < 3; pass++) {
        uint32_t sA = sbase + (pass == 2 ? SM_ALO : SM_AHI) + a_lane;
        uint32_t sW = sbase + (pass == 1 ? SM_WLO : SM_WHI) + b_lane;
#pragma unroll
        for (int k0 = 0; k0 < 128; k0 += 16) {
            uint32_t af[4][4], bf[4][2];
#pragma unroll
            for (int mi = 0; mi < 4; mi++)
                ldm_x4(af[mi], sA + mi * 16 * PITCH + k0 * 2);
#pragma unroll
            for (int nj = 0; nj < 4; nj++)
                ldm_x2(bf[nj], sW + nj * 8 * PITCH + k0 * 2);
#pragma unroll
            for (int mi = 0; mi < 4; mi++)
#pragma unroll
                for (int nj = 0; nj < 4; nj++)
                    mma_bf16(acc[mi][nj], af[mi], bf[nj]);
        }
    }

    // ---- Epilogue: bias + optional ReLU, direct global store ----
#pragma unroll
    for (int mi = 0; mi < 4; mi++) {
#pragma unroll
        for (int h = 0; h < 2; h++) {
            int gr = rowbase + warp_m + mi * 16 + h * 8 + (lane >> 2);
            if (gr < outRows) {
#pragma unroll
                for (int nj = 0; nj < 4; nj++) {
                    int c = warp_n + nj * 8 + (lane & 3) * 2;
                    float v0 = acc[mi][nj][h * 2 + 0] + bias[c];
                    float v1 = acc[mi][nj][h * 2 + 1] + bias[c + 1];
                    if (doRelu) { v0 = fmaxf(v0, 0.0f); v1 = fmaxf(v1, 0.0f); }
                    float2 o = make_float2(v0, v1);
                    *(float2*)&C[(size_t)gr * DIM + c] = o;
                }
            }
        }
    }
}

// ---------------------------------------------------------------------------
// Host launcher
// ---------------------------------------------------------------------------
extern "C" void kernel_launch(void* const* d_in, const int* in_sizes, int n_in,
                              void* d_out, int out_size) {
    const float* x   = (const float*)d_in[0];
    const int*   src = (const int*)  d_in[1];
    const int*   dst = (const int*)  d_in[2];
    const float* W1  = (const float*)d_in[3];
    const float* b1  = (const float*)d_in[4];
    const float* W2  = (const float*)d_in[5];
    const float* b2  = (const float*)d_in[6];
    float* out = (float*)d_out;

    float *z, *hid, *h;
    __nv_bfloat16 *w1hi, *w1lo, *w2hi, *w2lo;
    cudaGetSymbolAddress((void**)&z,    g_z);
    cudaGetSymbolAddress((void**)&hid,  g_hid);
    cudaGetSymbolAddress((void**)&h,    g_h);
    cudaGetSymbolAddress((void**)&w1hi, g_w1hi);
    cudaGetSymbolAddress((void**)&w1lo, g_w1lo);
    cudaGetSymbolAddress((void**)&w2hi, g_w2hi);
    cudaGetSymbolAddress((void**)&w2lo, g_w2lo);

    cudaFuncSetAttribute(gemm_tc_kernel, cudaFuncAttributeMaxDynamicSharedMemorySize, SMEM_DYN);

    // CSR build
    clear_counts_kernel<<<(NN + 255) / 256, 256>>>();
    hist_kernel<<<(NE + 255) / 256, 256>>>(dst);
    scan_kernel<<<1, 1024>>>();
    fill_kernel<<<(NE + 255) / 256, 256>>>(src, dst);

    // Weight splits (transposed, bf16 hi/lo)
    wprep_kernel<<<64, 256>>>(W1, w1hi, w1lo);
    wprep_kernel<<<64, 256>>>(W2, w2hi, w2lo);

    const int gather_blocks = (NN * 32 + 255) / 256;

    const float* h_in = x;
    for (int layer = 0; layer < 3; layer++) {
        gather_kernel<<<gather_blocks, 256>>>(h_in, z);
        // hid = relu(z @ W1 + b1)
        gemm_tc_kernel<<<NT, 256, SMEM_DYN>>>(z, w1hi, w1lo, b1, hid, PADN, 1);
        if (layer < 2) {
            // h = relu(hid @ W2 + b2)  (inter-layer ReLU fused)
            gemm_tc_kernel<<<NT, 256, SMEM_DYN>>>(hid, w2hi, w2lo, b2, h, PADN, 1);
        } else {
            // out = hid @ W2 + b2 (no ReLU)
            gemm_tc_kernel<<<NT, 256, SMEM_DYN>>>(hid, w2hi, w2lo, b2, out, NN, 0);
        }
        h_in = h;
    }
}